// round 12
// baseline (speedup 1.0000x reference)
#include <cuda_runtime.h>
#include <cstdint>
#include <math.h>

// Problem constants
constexpr int NN    = 4096;          // number of vertices / matrix dim
constexpr int TPB   = 1024;          // threads per block
constexpr int SLICE = NN / TPB;      // 4 vertices per thread (per matrix)
constexpr int NWARP = TPB / 32;      // 32 warps

// Scratch (no allocations allowed): final Prim parent arrays for both matrices.
__device__ int g_parent[2][NN];

// ---------------------------------------------------------------------------
// Dual exact Prim's MST, BOTH matrices interleaved in ONE CTA (grid = 1).
//
// Rationale (R11): each MST iteration = serial reduction spine (~390ns) +
// exposed row-load latency (~300ns on spec misses), strictly serialized when
// each MST has its own CTA — the CTA idles during the load. Interleaving the
// two independent chains lets matrix-1's row-load latency hide under
// matrix-2's cross-reduction + runner-up work and vice versa, and one
// __syncthreads covers both matrices' partials (half the barriers per step).
//
// Thread t owns vertices [4t, 4t+4) of BOTH matrices.
//   mdX[k] : best edge weight from tree to vertex 4t+k (matrix X). Sign bit
//            set <=> in tree: strict float `rv < md` always fails vs negative
//            md, and its u32 pattern (>= 0x80000000) loses every unsigned min.
//   parX[k]: tree endpoint realizing mdX (frozen at pop).
//
// Argmin matches jnp.argmin (first index) exactly (u32 keys):
//   - lane-local: pmin = u32 min of md bit patterns (nonneg float bit order ==
//     value order); index = FIRST k with bits==wmin -> lowest vertex in lane.
//   - warp: REDUX.MIN + ballot; first matching lane == lowest vertex.
//   - cross-warp: warp order == vertex-range order; ballot/ffs again.
//
// Speculation (R8, kept, both matrices): next winner is the runner-up j2
// unless the fresh relaxation creates a new min; stage row j2 via cp.async
// into smem (128 lines/row — safe footprint; R7's 4096-line flood is the
// documented disaster). Buffers are single-buffered: thread t writes and
// reads only its own 16B slice, and the consuming LDS completes ~30cyc after
// issue while the overwriting LDGSTS lands >=500cyc later (no hazard).
// Register budget (R6 lesson, 64-reg cap at TPB=1024): ~50 live regs.
// ---------------------------------------------------------------------------
__global__ __launch_bounds__(TPB, 1)
void mst2_kernel(const float* __restrict__ d1, const float* __restrict__ d2) {
    const int t    = threadIdx.x;
    const int wid  = t >> 5;
    const int lane = t & 31;
    constexpr unsigned FULL = 0xFFFFFFFFu;

    // per-warp winner (bits, idx) per matrix, double-buffered across iterations
    __shared__ unsigned pb[2][2][NWARP];   // [matrix][buf][warp]
    __shared__ unsigned pi[2][2][NWARP];
    // speculative next-row buffers, one 16KB row per matrix (single-buffered)
    __shared__ __align__(16) float spec[2][NN];

    float md1[SLICE], md2[SLICE];
    int   par1[SLICE], par2[SLICE];

    // ---- init: min_dist = D[0, :], parent = 0, vertex 0 in tree (both) ----
    {
        float4 a = reinterpret_cast<const float4*>(d1)[t];
        md1[0] = a.x; md1[1] = a.y; md1[2] = a.z; md1[3] = a.w;
        float4 b = reinterpret_cast<const float4*>(d2)[t];
        md2[0] = b.x; md2[1] = b.y; md2[2] = b.z; md2[3] = b.w;
    }
#pragma unroll
    for (int k = 0; k < SLICE; ++k) { par1[k] = 0; par2[k] = 0; }
    if (t == 0) {
        md1[0] = __uint_as_float(0xFF800000u);   // vertex 0: -inf => in tree
        md2[0] = __uint_as_float(0xFF800000u);
    }

    unsigned pmin1 = 0xFFFFFFFFu, pmin2 = 0xFFFFFFFFu;
#pragma unroll
    for (int k = 0; k < SLICE; ++k) {
        pmin1 = min(pmin1, __float_as_uint(md1[k]));
        pmin2 = min(pmin2, __float_as_uint(md2[k]));
    }

    int si1 = -1, si2 = -1;   // row currently staged in spec[0] / spec[1]

    for (int sel = 0; sel < NN - 1; ++sel) {
        const int s = sel & 1;

        // ---- warp phase, matrix 1 ----
        {
            const unsigned wmin = __reduce_min_sync(FULL, pmin1);
            const unsigned ball = __ballot_sync(FULL, pmin1 == wmin);
            const int      wsrc = __ffs((int)ball) - 1;
            if (lane == wsrc) {
                int k0 = (__float_as_uint(md1[0]) == wmin) ? 0
                       : (__float_as_uint(md1[1]) == wmin) ? 1
                       : (__float_as_uint(md1[2]) == wmin) ? 2 : 3;
                pb[0][s][wid] = wmin;
                pi[0][s][wid] = (unsigned)(t * SLICE + k0);
            }
        }
        // ---- warp phase, matrix 2 ----
        {
            const unsigned wmin = __reduce_min_sync(FULL, pmin2);
            const unsigned ball = __ballot_sync(FULL, pmin2 == wmin);
            const int      wsrc = __ffs((int)ball) - 1;
            if (lane == wsrc) {
                int k0 = (__float_as_uint(md2[0]) == wmin) ? 0
                       : (__float_as_uint(md2[1]) == wmin) ? 1
                       : (__float_as_uint(md2[2]) == wmin) ? 2 : 3;
                pb[1][s][wid] = wmin;
                pi[1][s][wid] = (unsigned)(t * SLICE + k0);
            }
        }
        __syncthreads();   // ONE barrier for both matrices

        // ---- cross-warp phase, matrix 1 -> j1 ----
        const unsigned b1 = pb[0][s][lane];
        const unsigned i1 = pi[0][s][lane];
        const unsigned g1 = __reduce_min_sync(FULL, b1);
        const int src1 = __ffs((int)__ballot_sync(FULL, b1 == g1)) - 1;
        const int j1   = (int)__shfl_sync(FULL, i1, src1);

        // ---- cross-warp phase, matrix 2 -> j2m ----
        const unsigned b2 = pb[1][s][lane];
        const unsigned i2 = pi[1][s][lane];
        const unsigned g2 = __reduce_min_sync(FULL, b2);
        const int src2 = __ffs((int)__ballot_sync(FULL, b2 == g2)) - 1;
        const int j2m  = (int)__shfl_sync(FULL, i2, src2);

        // owners mark winners in-tree (sign-bit flip), static indexing only
        if ((j1 >> 2) == t) {
#pragma unroll
            for (int k = 0; k < SLICE; ++k)
                if (k == (j1 & (SLICE - 1)))
                    md1[k] = __uint_as_float(__float_as_uint(md1[k]) | 0x80000000u);
        }
        if ((j2m >> 2) == t) {
#pragma unroll
            for (int k = 0; k < SLICE; ++k)
                if (k == (j2m & (SLICE - 1)))
                    md2[k] = __uint_as_float(__float_as_uint(md2[k]) | 0x80000000u);
        }
        if (sel == NN - 2) break;   // last vertices popped, no relaxation needed

        // ---- row data (hits read staged smem; misses issue LDG now).
        //      Both reads happen BEFORE any new cp.async is issued. ----
        float4 a1, a2;
        const bool hit1 = (j1 == si1), hit2 = (j2m == si2);
        if (hit1 || hit2)
            asm volatile("cp.async.wait_all;" ::: "memory");  // drains last iter's stages
        if (hit1) a1 = reinterpret_cast<const float4*>(&spec[0][0])[t];
        else      a1 = reinterpret_cast<const float4*>(d1 + (size_t)j1 * NN)[t];
        if (hit2) a2 = reinterpret_cast<const float4*>(&spec[1][0])[t];
        else      a2 = reinterpret_cast<const float4*>(d2 + (size_t)j2m * NN)[t];

        // ---- runner-ups (next-winner predictions): stage both rows ----
        {
            const unsigned bx   = (lane == src1) ? 0xFFFFFFFFu : b1;
            const unsigned gmx  = __reduce_min_sync(FULL, bx);
            const int srcx = __ffs((int)__ballot_sync(FULL, bx == gmx)) - 1;
            const int r1   = (int)__shfl_sync(FULL, i1, srcx);
            si1 = r1;
            const float* gsrc = d1 + (size_t)r1 * NN + t * 4;
            const unsigned dsts =
                (unsigned)__cvta_generic_to_shared(&spec[0][0]) + (unsigned)(t * 16);
            asm volatile("cp.async.cg.shared.global [%0], [%1], 16;\n"
                         :: "r"(dsts), "l"(gsrc) : "memory");
        }
        {
            const unsigned bx   = (lane == src2) ? 0xFFFFFFFFu : b2;
            const unsigned gmx  = __reduce_min_sync(FULL, bx);
            const int srcx = __ffs((int)__ballot_sync(FULL, bx == gmx)) - 1;
            const int r2   = (int)__shfl_sync(FULL, i2, srcx);
            si2 = r2;
            const float* gsrc = d2 + (size_t)r2 * NN + t * 4;
            const unsigned dsts =
                (unsigned)__cvta_generic_to_shared(&spec[1][0]) + (unsigned)(t * 16);
            asm volatile("cp.async.cg.shared.global [%0], [%1], 16;\n"
                         "cp.async.commit_group;\n" :: "r"(dsts), "l"(gsrc) : "memory");
        }

        // ---- relax matrix 1 (strict float <, matches reference) ----
        {
            float rv[SLICE] = {a1.x, a1.y, a1.z, a1.w};
            pmin1 = 0xFFFFFFFFu;
#pragma unroll
            for (int k = 0; k < SLICE; ++k) {
                if (rv[k] < md1[k]) { md1[k] = rv[k]; par1[k] = j1; }
                pmin1 = min(pmin1, __float_as_uint(md1[k]));
            }
        }
        // ---- relax matrix 2 ----
        {
            float rv[SLICE] = {a2.x, a2.y, a2.z, a2.w};
            pmin2 = 0xFFFFFFFFu;
#pragma unroll
            for (int k = 0; k < SLICE; ++k) {
                if (rv[k] < md2[k]) { md2[k] = rv[k]; par2[k] = j2m; }
                pmin2 = min(pmin2, __float_as_uint(md2[k]));
            }
        }
    }

    // drain any outstanding speculative copies before smem goes away
    asm volatile("cp.async.wait_all;" ::: "memory");

    // parents are frozen at pop time; write once at the end
#pragma unroll
    for (int k = 0; k < SLICE; ++k) {
        g_parent[0][t * SLICE + k] = par1[k];
        g_parent[1][t * SLICE + k] = par2[k];
    }
}

// ---------------------------------------------------------------------------
// Gather signatures, fp64 sums, sqrt, matched-pair count.
// Each child c in 1..N-1 appears exactly once in each pair list, so
// matched_pairs = #{ c : parent1[c] == parent2[c] }.
// ---------------------------------------------------------------------------
__global__ __launch_bounds__(1024)
void finalize_kernel(const float* __restrict__ d1, const float* __restrict__ d2,
                     float* __restrict__ out, int out_size) {
    constexpr int FT = 1024;
    __shared__ double s12[FT];
    __shared__ double s21[FT];
    __shared__ int    sm[FT];
    const int t = threadIdx.x;

    double a12 = 0.0, a21 = 0.0;
    int m = 0;
#pragma unroll
    for (int i = 0; i < 4; ++i) {
        int c = 1 + t + i * FT;
        if (c < NN) {
            int p1 = g_parent[0][c];
            int p2 = g_parent[1][c];
            float x1 = d1[(size_t)p1 * NN + c];   // sig1
            float y1 = d2[(size_t)p1 * NN + c];   // sig1_2
            float x2 = d2[(size_t)p2 * NN + c];   // sig2
            float y2 = d1[(size_t)p2 * NN + c];   // sig2_1
            double e1 = (double)x1 - (double)y1;
            double e2 = (double)x2 - (double)y2;
            a12 += e1 * e1;
            a21 += e2 * e2;
            m += (p1 == p2);
        }
    }
    s12[t] = a12; s21[t] = a21; sm[t] = m;
    __syncthreads();
#pragma unroll
    for (int o = FT / 2; o; o >>= 1) {
        if (t < o) {
            s12[t] += s12[t + o];
            s21[t] += s21[t + o];
            sm[t]  += sm[t + o];
        }
        __syncthreads();
    }
    if (t == 0) {
        double D12 = sqrt(s12[0]);
        double D21 = sqrt(s21[0]);
        if (out_size > 0) out[0] = (float)(D12 + D21);   // distance
        if (out_size > 1) out[1] = (float)D12;           // distance1_2
        if (out_size > 2) out[2] = (float)D21;           // distance2_1
        if (out_size > 3) out[3] = (float)sm[0];         // matched_pairs
    }
}

extern "C" void kernel_launch(void* const* d_in, const int* in_sizes, int n_in,
                              void* d_out, int out_size) {
    const float* d1 = (const float*)d_in[0];   // distances1 [4096,4096] f32
    const float* d2 = (const float*)d_in[1];   // distances2 [4096,4096] f32
    float* out = (float*)d_out;

    // Both exact Prim's MSTs interleaved in one CTA: each matrix's row-load
    // latency hides under the other matrix's reduction work.
    mst2_kernel<<<1, TPB>>>(d1, d2);
    // Tiny epilogue: gathers + fp64 reductions + matched-pair count.
    finalize_kernel<<<1, 1024>>>(d1, d2, out, out_size);
}

// round 13
// speedup vs baseline: 1.6255x; 1.6255x over previous
#include <cuda_runtime.h>
#include <cstdint>
#include <math.h>

// Problem constants
constexpr int NN    = 4096;          // number of vertices / matrix dim
constexpr int TPB   = 1024;          // threads per MST block
constexpr int SLICE = NN / TPB;      // 4 vertices per thread
constexpr int NWARP = TPB / 32;      // 32 warps

// Scratch (no allocations allowed).
__device__ int g_parent[2][NN];
__device__ int g_nn[2][NN];          // nearest neighbor of each vertex, per matrix

__device__ __forceinline__ unsigned long long u64min(unsigned long long a, unsigned long long b) {
    return b < a ? b : a;
}

// ---------------------------------------------------------------------------
// Preprocessing: g_nn[m][v] = argmin over row v (diagonal excluded).
// One warp per row, 8192 warps total; DRAM-bound, ~26us for 128MB.
// Pure heuristic input for speculation — does NOT touch MST correctness.
// ---------------------------------------------------------------------------
__global__ __launch_bounds__(256)
void nn_kernel(const float* __restrict__ d1, const float* __restrict__ d2) {
    const int wglob = (blockIdx.x * blockDim.x + threadIdx.x) >> 5;
    const int lane  = threadIdx.x & 31;
    const int m     = wglob >> 12;           // 0 or 1
    const int row   = wglob & (NN - 1);
    if (m > 1) return;
    const float* __restrict__ D = m ? d2 : d1;

    const float4* r4 = reinterpret_cast<const float4*>(D + (size_t)row * NN);
    unsigned long long key = ~0ull;
    for (int i = lane; i < NN / 4; i += 32) {
        float4 v = r4[i];
        const int base = i * 4;
        float  e[4] = {v.x, v.y, v.z, v.w};
#pragma unroll
        for (int k = 0; k < 4; ++k) {
            const int idx = base + k;
            if (idx != row) {
                unsigned long long kk =
                    ((unsigned long long)__float_as_uint(e[k]) << 32) | (unsigned)idx;
                key = u64min(key, kk);
            }
        }
    }
#pragma unroll
    for (int o = 16; o; o >>= 1)
        key = u64min(key, __shfl_xor_sync(0xFFFFFFFFu, key, o));
    if (lane == 0) g_nn[m][row] = (int)(unsigned)(key & 0xFFFFFFFFu);
}

// ---------------------------------------------------------------------------
// Exact Prim's MST, one persistent CTA per matrix (gridDim.x == 2).
// Core logic is byte-identical to R8 (best, rel_err 0.0): u64 keys, REDUX
// warp phase, single barrier, cross-warp redundant phase, sign-bit in-tree
// encoding, strict float < relaxation.
//
// Speculation (R12): TWO predicted next rows are staged into smem each
// iteration via cp.async:
//   specA <- j2     (global runner-up: next winner when relax does NOT win)
//   specB <- nn[j]  (nearest neighbor of the fresh pop: next winner when the
//                    relax DOES win — the ~70% case the j2 predictor misses)
// Footprint: <=384 lines/iter (2 stages + miss LDG) — far under the R7
// 4096-line flood. Buffers single-buffered; an UNCONDITIONAL wait_all once
// per iteration guarantees at most one outstanding copy per address (the
// previous iteration's copies had a full iteration to land). Hit branches
// are block-uniform. Pop sequence is unaffected: staging only changes WHERE
// bytes of constant D are read from.
// R6 lesson: no persistent register state beyond two ints. R9 lesson: no
// full-matrix L2 warming (128MB > 126MB L2, self-evicting).
// ---------------------------------------------------------------------------
__global__ __launch_bounds__(TPB, 1)
void mst_kernel(const float* __restrict__ d1, const float* __restrict__ d2) {
    const float* __restrict__ D  = blockIdx.x ? d2 : d1;
    const int*   __restrict__ nn = g_nn[blockIdx.x];
    const int t    = threadIdx.x;
    const int wid  = t >> 5;
    const int lane = t & 31;
    constexpr unsigned FULL = 0xFFFFFFFFu;

    // per-warp winner (bits, idx), double-buffered across iterations
    __shared__ unsigned pb[2][NWARP];
    __shared__ unsigned pi[2][NWARP];
    // speculative next-row buffers: A = runner-up j2, B = nn[j]  (16KB each)
    __shared__ __align__(16) float specA[NN];
    __shared__ __align__(16) float specB[NN];

    float md[SLICE];
    int   par[SLICE];

    // ---- init: min_dist = D[0, :], parent = 0, vertex 0 in tree ----
    {
        float4 a = reinterpret_cast<const float4*>(D)[t];
        md[0] = a.x; md[1] = a.y; md[2] = a.z; md[3] = a.w;
    }
#pragma unroll
    for (int k = 0; k < SLICE; ++k) par[k] = 0;
    if (t == 0) md[0] = __uint_as_float(0xFF800000u);   // vertex 0: -inf => in tree

    // thread-local argmin key over owned slice (u64: first-index tie-break)
    unsigned long long key = ~0ull;
#pragma unroll
    for (int k = 0; k < SLICE; ++k) {
        unsigned long long kk =
            ((unsigned long long)__float_as_uint(md[k]) << 32) | (unsigned)(t * SLICE + k);
        key = u64min(key, kk);
    }

    int siA = -1, siB = -1;   // rows staged in specA / specB (uniform)

    for (int sel = 0; sel < NN - 1; ++sel) {
        const int s = sel & 1;
        const unsigned bits = (unsigned)(key >> 32);
        const unsigned idx  = (unsigned)key;

        // ---- warp phase: single-instruction min + first-matching-lane store ----
        const unsigned wmin = __reduce_min_sync(FULL, bits);
        const unsigned ball = __ballot_sync(FULL, bits == wmin);
        const int      wsrc = __ffs((int)ball) - 1;   // first lane == lowest vertex on ties
        if (lane == wsrc) {
            pb[s][wid] = bits;
            pi[s][wid] = idx;
        }
        __syncthreads();

        // ---- cross-warp phase: 32 partials, one per lane ----
        const unsigned b2 = pb[s][lane];
        const unsigned i2 = pi[s][lane];
        const unsigned gmin  = __reduce_min_sync(FULL, b2);
        const unsigned ball2 = __ballot_sync(FULL, b2 == gmin);
        const int src = __ffs((int)ball2) - 1;            // lowest warp id with min
        const int j   = (int)__shfl_sync(FULL, i2, src);  // broadcast winner index

        // owner marks j in-tree (sign-bit flip), static register indexing only
        if ((j >> 2) == t) {
#pragma unroll
            for (int k = 0; k < SLICE; ++k)
                if (k == (j & (SLICE - 1)))
                    md[k] = __uint_as_float(__float_as_uint(md[k]) | 0x80000000u);
        }
        if (sel == NN - 2) break;   // last vertex popped, no relaxation needed

        // ---- drain last iteration's stages (unconditional: guarantees no two
        //      outstanding copies to the same smem address; usually a no-op) ----
        asm volatile("cp.async.wait_all;" ::: "memory");

        // ---- row-j data: two speculation targets, then global fallback ----
        float4 a;
        if (j == siA) {
            a = reinterpret_cast<const float4*>(&specA[0])[t];
        } else if (j == siB) {
            a = reinterpret_cast<const float4*>(&specB[0])[t];
        } else {
            a = reinterpret_cast<const float4*>(D + (size_t)j * NN)[t];  // issue now
        }

        // ---- stage A: global runner-up j2 (covers no-relax-win case) ----
        {
            const unsigned bx  = (lane == src) ? 0xFFFFFFFFu : b2;
            const unsigned gm2 = __reduce_min_sync(FULL, bx);
            const int srcx = __ffs((int)__ballot_sync(FULL, bx == gm2)) - 1;
            const int j2   = (int)__shfl_sync(FULL, i2, srcx);
            siA = j2;
            const float* gsrc = D + (size_t)j2 * NN + t * 4;
            const unsigned dsts =
                (unsigned)__cvta_generic_to_shared(&specA[0]) + (unsigned)(t * 16);
            asm volatile("cp.async.cg.shared.global [%0], [%1], 16;\n"
                         :: "r"(dsts), "l"(gsrc) : "memory");
        }
        // ---- stage B: nn[j] (covers relax-win case: fresh pop's nearest nbr) ----
        {
            const int nj = __ldg(&nn[j]);   // uniform scalar, hot in L1/L2
            siB = nj;
            const float* gsrc = D + (size_t)nj * NN + t * 4;
            const unsigned dsts =
                (unsigned)__cvta_generic_to_shared(&specB[0]) + (unsigned)(t * 16);
            asm volatile("cp.async.cg.shared.global [%0], [%1], 16;\n"
                         "cp.async.commit_group;\n" :: "r"(dsts), "l"(gsrc) : "memory");
        }

        // ---- relax with row j, fused with local argmin recompute (R8 form) ----
        float rv[SLICE] = {a.x, a.y, a.z, a.w};
        key = ~0ull;
#pragma unroll
        for (int k = 0; k < SLICE; ++k) {
            if (rv[k] < md[k]) { md[k] = rv[k]; par[k] = j; }   // strict <, matches reference
            unsigned long long kk =
                ((unsigned long long)__float_as_uint(md[k]) << 32) | (unsigned)(t * SLICE + k);
            key = u64min(key, kk);
        }
    }

    // drain any outstanding speculative copies before smem goes away
    asm volatile("cp.async.wait_all;" ::: "memory");

    // parents are frozen at pop time; write once at the end
#pragma unroll
    for (int k = 0; k < SLICE; ++k)
        g_parent[blockIdx.x][t * SLICE + k] = par[k];
}

// ---------------------------------------------------------------------------
// Gather signatures, fp64 sums, sqrt, matched-pair count.
// Each child c in 1..N-1 appears exactly once in each pair list, so
// matched_pairs = #{ c : parent1[c] == parent2[c] }.
// ---------------------------------------------------------------------------
__global__ __launch_bounds__(1024)
void finalize_kernel(const float* __restrict__ d1, const float* __restrict__ d2,
                     float* __restrict__ out, int out_size) {
    constexpr int FT = 1024;
    __shared__ double s12[FT];
    __shared__ double s21[FT];
    __shared__ int    sm[FT];
    const int t = threadIdx.x;

    double a12 = 0.0, a21 = 0.0;
    int m = 0;
#pragma unroll
    for (int i = 0; i < 4; ++i) {
        int c = 1 + t + i * FT;
        if (c < NN) {
            int p1 = g_parent[0][c];
            int p2 = g_parent[1][c];
            float x1 = d1[(size_t)p1 * NN + c];   // sig1
            float y1 = d2[(size_t)p1 * NN + c];   // sig1_2
            float x2 = d2[(size_t)p2 * NN + c];   // sig2
            float y2 = d1[(size_t)p2 * NN + c];   // sig2_1
            double e1 = (double)x1 - (double)y1;
            double e2 = (double)x2 - (double)y2;
            a12 += e1 * e1;
            a21 += e2 * e2;
            m += (p1 == p2);
        }
    }
    s12[t] = a12; s21[t] = a21; sm[t] = m;
    __syncthreads();
#pragma unroll
    for (int o = FT / 2; o; o >>= 1) {
        if (t < o) {
            s12[t] += s12[t + o];
            s21[t] += s21[t + o];
            sm[t]  += sm[t + o];
        }
        __syncthreads();
    }
    if (t == 0) {
        double D12 = sqrt(s12[0]);
        double D21 = sqrt(s21[0]);
        if (out_size > 0) out[0] = (float)(D12 + D21);   // distance
        if (out_size > 1) out[1] = (float)D12;           // distance1_2
        if (out_size > 2) out[2] = (float)D21;           // distance2_1
        if (out_size > 3) out[3] = (float)sm[0];         // matched_pairs
    }
}

extern "C" void kernel_launch(void* const* d_in, const int* in_sizes, int n_in,
                              void* d_out, int out_size) {
    const float* d1 = (const float*)d_in[0];   // distances1 [4096,4096] f32
    const float* d2 = (const float*)d_in[1];   // distances2 [4096,4096] f32
    float* out = (float*)d_out;

    // 1) Nearest-neighbor table for speculation (~26us, fully parallel).
    nn_kernel<<<1024, 256>>>(d1, d2);
    // 2) Two persistent CTAs, one exact Prim's MST each (runs concurrently).
    mst_kernel<<<2, TPB>>>(d1, d2);
    // 3) Tiny epilogue: gathers + fp64 reductions + matched-pair count.
    finalize_kernel<<<1, 1024>>>(d1, d2, out, out_size);
}

// round 14
// speedup vs baseline: 1.6473x; 1.0134x over previous
#include <cuda_runtime.h>
#include <cstdint>
#include <math.h>

// Problem constants
constexpr int NN    = 4096;          // number of vertices / matrix dim
constexpr int TPB   = 1024;          // threads per MST block
constexpr int SLICE = NN / TPB;      // 4 vertices per thread
constexpr int NWARP = TPB / 32;      // 32 warps

// Scratch (no allocations allowed).
__device__ int g_parent[2][NN];
__device__ int g_nn[2][NN];          // nearest neighbor of each vertex, per matrix

__device__ __forceinline__ unsigned long long u64min(unsigned long long a, unsigned long long b) {
    return b < a ? b : a;
}

// ---------------------------------------------------------------------------
// Preprocessing: g_nn[m][v] = argmin over row v (diagonal excluded).
// One warp per row; DRAM-bound, measured 25us. Heuristic input for the
// prefetch hint only — never touches MST correctness.
// ---------------------------------------------------------------------------
__global__ __launch_bounds__(256)
void nn_kernel(const float* __restrict__ d1, const float* __restrict__ d2) {
    const int wglob = (blockIdx.x * blockDim.x + threadIdx.x) >> 5;
    const int lane  = threadIdx.x & 31;
    const int m     = wglob >> 12;           // 0 or 1
    const int row   = wglob & (NN - 1);
    if (m > 1) return;
    const float* __restrict__ D = m ? d2 : d1;

    const float4* r4 = reinterpret_cast<const float4*>(D + (size_t)row * NN);
    unsigned long long key = ~0ull;
    for (int i = lane; i < NN / 4; i += 32) {
        float4 v = r4[i];
        const int base = i * 4;
        float  e[4] = {v.x, v.y, v.z, v.w};
#pragma unroll
        for (int k = 0; k < 4; ++k) {
            const int idx = base + k;
            if (idx != row) {
                unsigned long long kk =
                    ((unsigned long long)__float_as_uint(e[k]) << 32) | (unsigned)idx;
                key = u64min(key, kk);
            }
        }
    }
#pragma unroll
    for (int o = 16; o; o >>= 1)
        key = u64min(key, __shfl_xor_sync(0xFFFFFFFFu, key, o));
    if (lane == 0) g_nn[m][row] = (int)(unsigned)(key & 0xFFFFFFFFu);
}

// ---------------------------------------------------------------------------
// Exact Prim's MST, one persistent CTA per matrix (gridDim.x == 2).
// Core loop is the R8 structure unchanged (best measured, rel_err 0.0):
// u64 keys, REDUX warp phase, one barrier, redundant cross-warp phase,
// sign-bit in-tree encoding, strict float < relaxation, and cp.async
// staging of the global runner-up j2 into double-buffered smem with a
// HIT-CONDITIONAL wait (R12's unconditional wait stalled every miss).
//
// R13 addition: after staging j2, prefetch.global.L2 the row of nn[j]
// (nearest neighbor of the fresh pop) — the likely next winner on
// relax-win iterations, which the j2 predictor structurally misses.
// Fire-and-forget hint: no buffer, no wait, no ordering, no correctness
// coupling. Footprint <=384 lines/iter (miss LDG + stage + hint) — far
// under the R7 4096-line flood.
// R6 lesson: no persistent register state. R9 lesson: no full-matrix
// L2 warming (128MB > 126MB L2).
// ---------------------------------------------------------------------------
__global__ __launch_bounds__(TPB, 1)
void mst_kernel(const float* __restrict__ d1, const float* __restrict__ d2) {
    const float* __restrict__ D  = blockIdx.x ? d2 : d1;
    const int*   __restrict__ nn = g_nn[blockIdx.x];
    const int t    = threadIdx.x;
    const int wid  = t >> 5;
    const int lane = t & 31;
    constexpr unsigned FULL = 0xFFFFFFFFu;

    // per-warp winner (bits, idx), double-buffered across iterations
    __shared__ unsigned pb[2][NWARP];
    __shared__ unsigned pi[2][NWARP];
    // speculative next-row buffers (double-buffered, 16KB each)
    __shared__ __align__(16) float specbuf[2][NN];

    float md[SLICE];
    int   par[SLICE];

    // ---- init: min_dist = D[0, :], parent = 0, vertex 0 in tree ----
    {
        float4 a = reinterpret_cast<const float4*>(D)[t];
        md[0] = a.x; md[1] = a.y; md[2] = a.z; md[3] = a.w;
    }
#pragma unroll
    for (int k = 0; k < SLICE; ++k) par[k] = 0;
    if (t == 0) md[0] = __uint_as_float(0xFF800000u);   // vertex 0: -inf => in tree

    // thread-local argmin key over owned slice (u64: first-index tie-break)
    unsigned long long key = ~0ull;
#pragma unroll
    for (int k = 0; k < SLICE; ++k) {
        unsigned long long kk =
            ((unsigned long long)__float_as_uint(md[k]) << 32) | (unsigned)(t * SLICE + k);
        key = u64min(key, kk);
    }

    int spec_idx = -1;   // row currently (being) staged in specbuf[(sel-1)&1]

    for (int sel = 0; sel < NN - 1; ++sel) {
        const int s = sel & 1;
        const unsigned bits = (unsigned)(key >> 32);
        const unsigned idx  = (unsigned)key;

        // ---- warp phase: single-instruction min + first-matching-lane store ----
        const unsigned wmin = __reduce_min_sync(FULL, bits);
        const unsigned ball = __ballot_sync(FULL, bits == wmin);
        const int      wsrc = __ffs((int)ball) - 1;   // first lane == lowest vertex on ties
        if (lane == wsrc) {
            pb[s][wid] = bits;
            pi[s][wid] = idx;
        }
        __syncthreads();

        // ---- cross-warp phase: 32 partials, one per lane ----
        const unsigned b2 = pb[s][lane];
        const unsigned i2 = pi[s][lane];
        const unsigned gmin  = __reduce_min_sync(FULL, b2);
        const unsigned ball2 = __ballot_sync(FULL, b2 == gmin);
        const int src = __ffs((int)ball2) - 1;            // lowest warp id with min
        const int j   = (int)__shfl_sync(FULL, i2, src);  // broadcast winner index

        // owner marks j as in-tree (sign-bit flip), static register indexing only
        if ((j >> 2) == t) {
#pragma unroll
            for (int k = 0; k < SLICE; ++k)
                if (k == (j & (SLICE - 1)))
                    md[k] = __uint_as_float(__float_as_uint(md[k]) | 0x80000000u);
        }
        if (sel == NN - 2) break;   // last vertex popped, no relaxation needed

        // ---- row-j data: speculation hit => staged in smem (block-uniform) ----
        float4 a;
        if (j == spec_idx) {
            // this thread staged its own 16B slice; thread-local wait suffices
            asm volatile("cp.async.wait_all;" ::: "memory");
            a = reinterpret_cast<const float4*>(&specbuf[s ^ 1][0])[t];  // written at sel-1
        } else {
            a = reinterpret_cast<const float4*>(D + (size_t)j * NN)[t];  // issue now
        }

        // ---- stage A: runner-up j2 via cp.async (covers no-relax-win case).
        //      Chain + LDGSTS hide under the in-flight row load on misses. ----
        {
            const unsigned b2x   = (lane == src) ? 0xFFFFFFFFu : b2;
            const unsigned gmin2 = __reduce_min_sync(FULL, b2x);
            const unsigned ball3 = __ballot_sync(FULL, b2x == gmin2);
            const int src2 = __ffs((int)ball3) - 1;
            const int j2   = (int)__shfl_sync(FULL, i2, src2);
            spec_idx = j2;
            const float* gsrc = D + (size_t)j2 * NN + t * 4;
            const unsigned dsts =
                (unsigned)__cvta_generic_to_shared(&specbuf[s][0]) + (unsigned)(t * 16);
            asm volatile("cp.async.cg.shared.global [%0], [%1], 16;\n"
                         "cp.async.commit_group;\n" :: "r"(dsts), "l"(gsrc) : "memory");
        }

        // ---- hint B: nn[j] row -> L2 (covers relax-win case). Fire-and-forget:
        //      no buffer, no wait, no correctness coupling. 128 lines. ----
        {
            const int nj = __ldg(&nn[j]);   // 16KB table, hot after first sweeps
            if (t < NN / 32) {              // 128 threads x one 128B line = full row
                const char* p = reinterpret_cast<const char*>(D + (size_t)nj * NN) + t * 128;
                asm volatile("prefetch.global.L2 [%0];" :: "l"(p));
            }
        }

        // ---- relax with row j, fused with local argmin recompute ----
        float rv[SLICE] = {a.x, a.y, a.z, a.w};
        key = ~0ull;
#pragma unroll
        for (int k = 0; k < SLICE; ++k) {
            if (rv[k] < md[k]) { md[k] = rv[k]; par[k] = j; }   // strict <, matches reference
            unsigned long long kk =
                ((unsigned long long)__float_as_uint(md[k]) << 32) | (unsigned)(t * SLICE + k);
            key = u64min(key, kk);
        }
    }

    // drain any outstanding speculative copies before smem goes away
    asm volatile("cp.async.wait_all;" ::: "memory");

    // parents are frozen at pop time; write once at the end
#pragma unroll
    for (int k = 0; k < SLICE; ++k)
        g_parent[blockIdx.x][t * SLICE + k] = par[k];
}

// ---------------------------------------------------------------------------
// Gather signatures, fp64 sums, sqrt, matched-pair count.
// Each child c in 1..N-1 appears exactly once in each pair list, so
// matched_pairs = #{ c : parent1[c] == parent2[c] }.
// ---------------------------------------------------------------------------
__global__ __launch_bounds__(1024)
void finalize_kernel(const float* __restrict__ d1, const float* __restrict__ d2,
                     float* __restrict__ out, int out_size) {
    constexpr int FT = 1024;
    __shared__ double s12[FT];
    __shared__ double s21[FT];
    __shared__ int    sm[FT];
    const int t = threadIdx.x;

    double a12 = 0.0, a21 = 0.0;
    int m = 0;
#pragma unroll
    for (int i = 0; i < 4; ++i) {
        int c = 1 + t + i * FT;
        if (c < NN) {
            int p1 = g_parent[0][c];
            int p2 = g_parent[1][c];
            float x1 = d1[(size_t)p1 * NN + c];   // sig1
            float y1 = d2[(size_t)p1 * NN + c];   // sig1_2
            float x2 = d2[(size_t)p2 * NN + c];   // sig2
            float y2 = d1[(size_t)p2 * NN + c];   // sig2_1
            double e1 = (double)x1 - (double)y1;
            double e2 = (double)x2 - (double)y2;
            a12 += e1 * e1;
            a21 += e2 * e2;
            m += (p1 == p2);
        }
    }
    s12[t] = a12; s21[t] = a21; sm[t] = m;
    __syncthreads();
#pragma unroll
    for (int o = FT / 2; o; o >>= 1) {
        if (t < o) {
            s12[t] += s12[t + o];
            s21[t] += s21[t + o];
            sm[t]  += sm[t + o];
        }
        __syncthreads();
    }
    if (t == 0) {
        double D12 = sqrt(s12[0]);
        double D21 = sqrt(s21[0]);
        if (out_size > 0) out[0] = (float)(D12 + D21);   // distance
        if (out_size > 1) out[1] = (float)D12;           // distance1_2
        if (out_size > 2) out[2] = (float)D21;           // distance2_1
        if (out_size > 3) out[3] = (float)sm[0];         // matched_pairs
    }
}

extern "C" void kernel_launch(void* const* d_in, const int* in_sizes, int n_in,
                              void* d_out, int out_size) {
    const float* d1 = (const float*)d_in[0];   // distances1 [4096,4096] f32
    const float* d2 = (const float*)d_in[1];   // distances2 [4096,4096] f32
    float* out = (float*)d_out;

    // 1) Nearest-neighbor table for the prefetch hint (~25us, fully parallel).
    nn_kernel<<<1024, 256>>>(d1, d2);
    // 2) Two persistent CTAs, one exact Prim's MST each (runs concurrently).
    mst_kernel<<<2, TPB>>>(d1, d2);
    // 3) Tiny epilogue: gathers + fp64 reductions + matched-pair count.
    finalize_kernel<<<1, 1024>>>(d1, d2, out, out_size);
}

// round 15
// speedup vs baseline: 1.6655x; 1.0110x over previous
#include <cuda_runtime.h>
#include <cstdint>
#include <math.h>

// Problem constants
constexpr int NN    = 4096;          // number of vertices / matrix dim
constexpr int TPB   = 512;           // threads per MST block (R14: 1024 -> 512)
constexpr int SLICE = NN / TPB;      // 8 vertices per thread
constexpr int NWARP = TPB / 32;      // 16 warps

// Scratch (no allocations allowed): final Prim parent arrays for both matrices.
__device__ int g_parent[2][NN];

__device__ __forceinline__ unsigned long long u64min(unsigned long long a, unsigned long long b) {
    return b < a ? b : a;
}

// ---------------------------------------------------------------------------
// Exact Prim's MST, one persistent CTA per matrix (gridDim.x == 2).
// Logic is R8 (best measured, rel_err 0.0) with TPB=512/SLICE=8:
// the spine was issue-bandwidth-bound (32 warps x ~35 instr / 4 slots);
// halving warp count halves that component and the barrier arrival spread,
// while the 128-reg/thread ceiling at TPB=512 removes all spill pressure.
//
// Thread t owns vertices [8t, 8t+8).
//   md[k] : best edge weight from tree to vertex 8t+k. Sign bit set <=> vertex
//           in tree: strict float `rv < md` always fails vs negative md, and
//           its u32 pattern (>= 0x80000000) loses every unsigned min.
//   par[k]: tree endpoint realizing md (frozen once the vertex pops).
//
// Argmin matches jnp.argmin (first index) exactly:
//   - thread-local: u64 key (bits<<32 | idx), min keeps lowest idx on ties
//   - warp: REDUX.MIN on bits + ballot; first lane == lowest vertex on ties
//   - cross-warp: 16 partials mirrored to both half-warps (lane & 15 — the
//     R3 half-warp bug class, handled); ffs returns the lowest warp id.
//
// Speculation (R8, kept): stage the global runner-up j2's row via cp.async
// into double-buffered smem (32B/thread now). Hit-conditional wait only
// (R12's unconditional wait stalled every miss). 128 lines/iter footprint
// (R7's 4096-line flood is the documented disaster). nn-predictor retired:
// R12/R13 both measured negative.
// ---------------------------------------------------------------------------
__global__ __launch_bounds__(TPB, 1)
void mst_kernel(const float* __restrict__ d1, const float* __restrict__ d2) {
    const float* __restrict__ D = blockIdx.x ? d2 : d1;
    const int t    = threadIdx.x;
    const int wid  = t >> 5;
    const int lane = t & 31;
    constexpr unsigned FULL = 0xFFFFFFFFu;

    // per-warp winner (bits, idx), double-buffered across iterations
    __shared__ unsigned pb[2][NWARP];
    __shared__ unsigned pi[2][NWARP];
    // speculative next-row buffers (double-buffered, 16KB each)
    __shared__ __align__(16) float specbuf[2][NN];

    float md[SLICE];
    int   par[SLICE];

    // ---- init: min_dist = D[0, :], parent = 0, vertex 0 in tree ----
    {
        const float4* row = reinterpret_cast<const float4*>(D) + t * 2;
        float4 a = row[0];
        float4 b = row[1];
        md[0] = a.x; md[1] = a.y; md[2] = a.z; md[3] = a.w;
        md[4] = b.x; md[5] = b.y; md[6] = b.z; md[7] = b.w;
    }
#pragma unroll
    for (int k = 0; k < SLICE; ++k) par[k] = 0;
    if (t == 0) md[0] = __uint_as_float(0xFF800000u);   // vertex 0: -inf => in tree

    // thread-local argmin key over owned slice (u64: first-index tie-break)
    unsigned long long key = ~0ull;
#pragma unroll
    for (int k = 0; k < SLICE; ++k) {
        unsigned long long kk =
            ((unsigned long long)__float_as_uint(md[k]) << 32) | (unsigned)(t * SLICE + k);
        key = u64min(key, kk);
    }

    int spec_idx = -1;   // row currently (being) staged in specbuf[(sel-1)&1]

    for (int sel = 0; sel < NN - 1; ++sel) {
        const int s = sel & 1;
        const unsigned bits = (unsigned)(key >> 32);
        const unsigned idx  = (unsigned)key;

        // ---- warp phase: single-instruction min + first-matching-lane store ----
        const unsigned wmin = __reduce_min_sync(FULL, bits);
        const unsigned ball = __ballot_sync(FULL, bits == wmin);
        const int      wsrc = __ffs((int)ball) - 1;   // first lane == lowest vertex on ties
        if (lane == wsrc) {
            pb[s][wid] = bits;
            pi[s][wid] = idx;
        }
        __syncthreads();

        // ---- cross-warp phase: 16 partials, mirrored into both half-warps ----
        const int      pl = lane & (NWARP - 1);
        const unsigned b2 = pb[s][pl];
        const unsigned i2 = pi[s][pl];
        const unsigned gmin  = __reduce_min_sync(FULL, b2);
        const unsigned ball2 = __ballot_sync(FULL, b2 == gmin);
        const int src = __ffs((int)ball2) - 1;            // in [0,16): lowest warp id
        const int j   = (int)__shfl_sync(FULL, i2, src);  // broadcast winner index

        // owner marks j as in-tree (sign-bit flip), static register indexing only
        if ((j >> 3) == t) {
#pragma unroll
            for (int k = 0; k < SLICE; ++k)
                if (k == (j & (SLICE - 1)))
                    md[k] = __uint_as_float(__float_as_uint(md[k]) | 0x80000000u);
        }
        if (sel == NN - 2) break;   // last vertex popped, no relaxation needed

        // ---- row-j data: speculation hit => staged in smem (block-uniform) ----
        float4 a, b;
        if (j == spec_idx) {
            // this thread staged its own 32B slice; thread-local wait suffices
            asm volatile("cp.async.wait_all;" ::: "memory");
            const float4* sp = reinterpret_cast<const float4*>(&specbuf[s ^ 1][0]) + t * 2;
            a = sp[0];
            b = sp[1];
        } else {
            const float4* row = reinterpret_cast<const float4*>(D + (size_t)j * NN) + t * 2;
            a = row[0];
            b = row[1];
        }

        // ---- runner-up j2 (next-winner prediction): stage its row via cp.async.
        //      Mask BOTH mirror copies of the winner ((lane&15)==src). ----
        {
            const unsigned b2x   = (pl == src) ? 0xFFFFFFFFu : b2;
            const unsigned gmin2 = __reduce_min_sync(FULL, b2x);
            const unsigned ball3 = __ballot_sync(FULL, b2x == gmin2);
            const int src2 = __ffs((int)ball3) - 1;
            const int j2   = (int)__shfl_sync(FULL, i2, src2);
            spec_idx = j2;
            const float* gsrc = D + (size_t)j2 * NN + t * 8;
            const unsigned dsts =
                (unsigned)__cvta_generic_to_shared(&specbuf[s][0]) + (unsigned)(t * 32);
            asm volatile("cp.async.cg.shared.global [%0], [%1], 16;\n"
                         "cp.async.cg.shared.global [%2], [%3], 16;\n"
                         "cp.async.commit_group;\n"
                         :: "r"(dsts), "l"(gsrc), "r"(dsts + 16), "l"(gsrc + 4) : "memory");
        }

        // ---- relax with row j, fused with local argmin recompute ----
        float rv[SLICE] = {a.x, a.y, a.z, a.w, b.x, b.y, b.z, b.w};
        key = ~0ull;
#pragma unroll
        for (int k = 0; k < SLICE; ++k) {
            if (rv[k] < md[k]) { md[k] = rv[k]; par[k] = j; }   // strict <, matches reference
            unsigned long long kk =
                ((unsigned long long)__float_as_uint(md[k]) << 32) | (unsigned)(t * SLICE + k);
            key = u64min(key, kk);
        }
    }

    // drain any outstanding speculative copies before smem goes away
    asm volatile("cp.async.wait_all;" ::: "memory");

    // parents are frozen at pop time; write once at the end
#pragma unroll
    for (int k = 0; k < SLICE; ++k)
        g_parent[blockIdx.x][t * SLICE + k] = par[k];
}

// ---------------------------------------------------------------------------
// Gather signatures, fp64 sums, sqrt, matched-pair count.
// Each child c in 1..N-1 appears exactly once in each pair list, so
// matched_pairs = #{ c : parent1[c] == parent2[c] }.
// ---------------------------------------------------------------------------
__global__ __launch_bounds__(1024)
void finalize_kernel(const float* __restrict__ d1, const float* __restrict__ d2,
                     float* __restrict__ out, int out_size) {
    constexpr int FT = 1024;
    __shared__ double s12[FT];
    __shared__ double s21[FT];
    __shared__ int    sm[FT];
    const int t = threadIdx.x;

    double a12 = 0.0, a21 = 0.0;
    int m = 0;
#pragma unroll
    for (int i = 0; i < 4; ++i) {
        int c = 1 + t + i * FT;
        if (c < NN) {
            int p1 = g_parent[0][c];
            int p2 = g_parent[1][c];
            float x1 = d1[(size_t)p1 * NN + c];   // sig1
            float y1 = d2[(size_t)p1 * NN + c];   // sig1_2
            float x2 = d2[(size_t)p2 * NN + c];   // sig2
            float y2 = d1[(size_t)p2 * NN + c];   // sig2_1
            double e1 = (double)x1 - (double)y1;
            double e2 = (double)x2 - (double)y2;
            a12 += e1 * e1;
            a21 += e2 * e2;
            m += (p1 == p2);
        }
    }
    s12[t] = a12; s21[t] = a21; sm[t] = m;
    __syncthreads();
#pragma unroll
    for (int o = FT / 2; o; o >>= 1) {
        if (t < o) {
            s12[t] += s12[t + o];
            s21[t] += s21[t + o];
            sm[t]  += sm[t + o];
        }
        __syncthreads();
    }
    if (t == 0) {
        double D12 = sqrt(s12[0]);
        double D21 = sqrt(s21[0]);
        if (out_size > 0) out[0] = (float)(D12 + D21);   // distance
        if (out_size > 1) out[1] = (float)D12;           // distance1_2
        if (out_size > 2) out[2] = (float)D21;           // distance2_1
        if (out_size > 3) out[3] = (float)sm[0];         // matched_pairs
    }
}

extern "C" void kernel_launch(void* const* d_in, const int* in_sizes, int n_in,
                              void* d_out, int out_size) {
    const float* d1 = (const float*)d_in[0];   // distances1 [4096,4096] f32
    const float* d2 = (const float*)d_in[1];   // distances2 [4096,4096] f32
    float* out = (float*)d_out;

    // Two persistent CTAs, one exact Prim's MST each (runs concurrently).
    mst_kernel<<<2, TPB>>>(d1, d2);
    // Tiny epilogue: gathers + fp64 reductions + matched-pair count.
    finalize_kernel<<<1, 1024>>>(d1, d2, out, out_size);
}